// round 4
// baseline (speedup 1.0000x reference)
#include <cuda_runtime.h>
#include <cuda_bf16.h>
#include <cstdint>
#include <cstdio>

typedef __nv_bfloat16 bf16;

#define TT 4
#define NN 8192
#define HD 256
#define RPAD 8320        // 1 zero halo row + 8192 data + tail pad (zero)
#define KT 768           // extended K: [hi | lo | hi] x 256
#define BM 128
#define BN 256
#define BK 64
#define NCH 12           // 768/64
#define MV 126           // valid output rows per M-tile
#define MT 66            // ceil(8192/126)
#define PSTRIDE 258
#define SMEM_BYTES (BM*PSTRIDE*4)            // 132096 (P tile; aliases stages)
#define STAGE_BYTES ((BM*BK + BN*BK)*2)      // 49152
#define A_STAGE_BYTES (BM*BK*2)              // 16384

// ------------------- device scratch (zero-initialized at load) -------------
__device__ __align__(256) bf16 g_Xhi[(size_t)TT*RPAD*HD];
__device__ __align__(256) bf16 g_Xlo[(size_t)TT*RPAD*HD];
__device__ __align__(256) bf16 g_Ahi[(size_t)TT*RPAD*HD];
__device__ __align__(256) bf16 g_Alo[(size_t)TT*RPAD*HD];
__device__ __align__(256) bf16 g_Bhi[(size_t)TT*RPAD*HD];
__device__ __align__(256) bf16 g_Blo[(size_t)TT*RPAD*HD];
__device__ __align__(256) bf16 g_W1[HD*KT];
__device__ __align__(256) bf16 g_WL[(size_t)8*2048*KT];
__device__ float g_bcat[8*2048];
__device__ float g_tw[10];
__device__ float g_aw[3];
__device__ float g_psum[64*HD];
__device__ float g_pmax[64*HD];

// ------------------- PTX helpers -------------------------------------------
__device__ __forceinline__ void cp_async16(unsigned dst, const void* src) {
    asm volatile("cp.async.cg.shared.global [%0], [%1], 16;\n" :: "r"(dst), "l"(src));
}
__device__ __forceinline__ void cp_commit() {
    asm volatile("cp.async.commit_group;\n" ::);
}
template <int N>
__device__ __forceinline__ void cp_wait() {
    asm volatile("cp.async.wait_group %0;\n" :: "n"(N));
}
__device__ __forceinline__ void ldsm4(unsigned addr, unsigned& r0, unsigned& r1,
                                      unsigned& r2, unsigned& r3) {
    asm volatile("ldmatrix.sync.aligned.m8n8.x4.shared.b16 {%0,%1,%2,%3}, [%4];\n"
                 : "=r"(r0), "=r"(r1), "=r"(r2), "=r"(r3) : "r"(addr));
}
__device__ __forceinline__ void mma16816(float c[4], const unsigned a[4], const unsigned b[2]) {
    asm volatile(
        "mma.sync.aligned.m16n8k16.row.col.f32.bf16.bf16.f32 "
        "{%0,%1,%2,%3}, {%4,%5,%6,%7}, {%8,%9}, {%0,%1,%2,%3};\n"
        : "+f"(c[0]), "+f"(c[1]), "+f"(c[2]), "+f"(c[3])
        : "r"(a[0]), "r"(a[1]), "r"(a[2]), "r"(a[3]), "r"(b[0]), "r"(b[1]));
}
__device__ __forceinline__ unsigned swz(unsigned b) { return b ^ ((b >> 3) & 0x70); }

__device__ __forceinline__ bf16* sel_hi(int s) { return s==0 ? g_Xhi : (s==1 ? g_Ahi : g_Bhi); }
__device__ __forceinline__ bf16* sel_lo(int s) { return s==0 ? g_Xlo : (s==1 ? g_Alo : g_Blo); }

// ------------------- prep kernels ------------------------------------------
__global__ void k_prep(const float* __restrict__ ta, const float* __restrict__ aa) {
    if (threadIdx.x == 0) {
        for (int l = 0; l < 2; l++) {
            float m = -1e30f;
            for (int i = 0; i < 5; i++) m = fmaxf(m, ta[l*5+i]);
            float e[5], s = 0.f;
            for (int i = 0; i < 5; i++) { e[i] = expf(ta[l*5+i] - m); s += e[i]; }
            for (int i = 0; i < 5; i++) g_tw[l*5+i] = e[i] / s;
        }
        float m = -1e30f;
        for (int i = 0; i < 3; i++) m = fmaxf(m, aa[i]);
        float e[3], s = 0.f;
        for (int i = 0; i < 3; i++) { e[i] = expf(aa[i] - m); s += e[i]; }
        for (int i = 0; i < 3; i++) g_aw[i] = e[i] / s;
    }
}

__global__ void k_packx(const float* __restrict__ x) {
    size_t total = (size_t)TT * RPAD * HD;
    for (size_t i = (size_t)blockIdx.x * blockDim.x + threadIdx.x; i < total;
         i += (size_t)gridDim.x * blockDim.x) {
        int ch = (int)(i % HD);
        size_t r = i / HD;
        int p = (int)(r % RPAD);
        int t = (int)(r / RPAD);
        float v = 0.f;
        int n = p - 1;
        if (n >= 0 && n < NN) v = x[((size_t)t * NN + n) * HD + ch];
        bf16 hi = __float2bfloat16(v);
        float lo = v - __bfloat162float(hi);
        g_Xhi[i] = hi;
        g_Xlo[i] = __float2bfloat16(lo);
    }
}

__global__ void k_packw1(const float* __restrict__ w) {
    int i = blockIdx.x * blockDim.x + threadIdx.x;  // n*256 + k
    if (i >= HD * HD) return;
    int n = i >> 8, k = i & 255;
    float v = w[k * HD + n];            // lin1_w[k][n], [Din, H] row-major
    bf16 hi = __float2bfloat16(v);
    bf16 lo = __float2bfloat16(v - __bfloat162float(hi));
    g_W1[n*KT + k]       = hi;
    g_W1[n*KT + 256 + k] = hi;
    g_W1[n*KT + 512 + k] = lo;
}

__global__ void k_packwl(const float* __restrict__ lw,  const float* __restrict__ lb,
                         const float* __restrict__ rlw, const float* __restrict__ rlb,
                         const float* __restrict__ cw,  const float* __restrict__ cb,
                         const float* __restrict__ rcw, const float* __restrict__ rcb) {
    size_t i = (size_t)blockIdx.x * blockDim.x + threadIdx.x;  // over 8*2048*256
    if (i >= (size_t)8 * 2048 * 256) return;
    int k  = (int)(i & 255);
    int n  = (int)((i >> 8) & 2047);
    int lt = (int)(i >> 19);         // 0..7
    int l = lt >> 2, t = lt & 3;
    int j = n >> 3, op = n & 7;
    float v;
    if (op == 0)      v = lw[(l*256 + k)*256 + j];
    else if (op == 1) v = rlw[((l*4 + t)*256 + k)*256 + j];
    else if (op < 5)  { int kk = op - 2; v = cw[((l*256 + j)*256 + k)*3 + kk]; }
    else              { int kk = op - 5; v = rcw[(((l*4 + t)*256 + j)*256 + k)*3 + kk]; }
    bf16 hi = __float2bfloat16(v);
    bf16 lo = __float2bfloat16(v - __bfloat162float(hi));
    size_t base = ((size_t)lt * 2048 + n) * KT;
    g_WL[base + k]       = hi;
    g_WL[base + 256 + k] = hi;
    g_WL[base + 512 + k] = lo;
    if (k == 0) {
        float b = 0.f;
        if (op == 0)      b = lb[l*256 + j];
        else if (op == 1) b = rlb[(l*4 + t)*256 + j];
        else if (op == 3) b = cb[l*256 + j];
        else if (op == 6) b = rcb[(l*4 + t)*256 + j];
        g_bcat[lt*2048 + n] = b;
    }
}

// ------------------- fused GEMM + epilogue ---------------------------------
// P[128 x BN] = Aext[128 x 768] * Bext[BN x 768]^T  (Aext planes hi/lo/hi)
// mode 0: lin1 (BN tile covers all 256 channels, no relu/conv/identity)
// mode 1: layer (BN covers 32 channels x 8 op taps)
__global__ void __launch_bounds__(512, 1)
k_gemm(int abuf, int obuf, const float* __restrict__ bias1, int mode, int layer) {
    extern __shared__ char smem[];
    const int tid = threadIdx.x;
    const int wid = tid >> 5, lane = tid & 31;
    const int tn = blockIdx.x, tm = blockIdx.y, t = blockIdx.z;

    const bf16* Ah = sel_hi(abuf) + (size_t)t * RPAD * HD;
    const bf16* Al = sel_lo(abuf) + (size_t)t * RPAD * HD;
    const bf16* Bp = mode ? (g_WL + (size_t)(layer*4 + t) * 2048 * KT) : g_W1;
    bf16* Oh = sel_hi(obuf);
    bf16* Ol = sel_lo(obuf);

    const int row0 = tm * MV;   // global padded row of A-tile row 0
    unsigned sbase = (unsigned)__cvta_generic_to_shared(smem);

    float c[8][2][4];
#pragma unroll
    for (int a = 0; a < 8; a++)
#pragma unroll
        for (int b = 0; b < 2; b++)
#pragma unroll
            for (int i = 0; i < 4; i++) c[a][b][i] = 0.f;

    auto load_chunk = [&](int ck, int stage) {
        unsigned sA = sbase + stage * STAGE_BYTES;
        unsigned sB = sA + A_STAGE_BYTES;
        const bf16* Apl = (ck < 4) ? Ah : (ck < 8 ? Al : Ah);
        int kofs = (ck & 3) * 64;
#pragma unroll
        for (int i = 0; i < 2; i++) {
            int idx = tid + i * 512;          // 0..1023
            int r = idx >> 3, cc = idx & 7;
            const bf16* src = Apl + (size_t)(row0 + r) * HD + kofs + cc * 8;
            cp_async16(sA + swz((unsigned)(r * 128 + cc * 16)), src);
        }
        int kb = ck * 64;
#pragma unroll
        for (int i = 0; i < 4; i++) {
            int idx = tid + i * 512;          // 0..2047
            int r = idx >> 3, cc = idx & 7;
            const bf16* src = Bp + (size_t)(tn * BN + r) * KT + kb + cc * 8;
            cp_async16(sB + swz((unsigned)(r * 128 + cc * 16)), src);
        }
        cp_commit();
    };

    // ldmatrix address bases (k-offset XOR mask depends only on row)
    const int wm = wid & 3, wn = wid >> 2;
    unsigned abase[2], amask[2], bbase[4], bmask[4];
    const unsigned aK = (unsigned)((lane >> 4) * 16);        // bytes
    const unsigned bK = (unsigned)(((lane >> 3) & 1) * 16);  // bytes
    {
        int r = wm * 32 + ((lane >> 3) & 1) * 8 + (lane & 7);
#pragma unroll
        for (int mf = 0; mf < 2; mf++) {
            unsigned rb = (unsigned)((r + mf * 16) * 128);
            abase[mf] = rb;
            amask[mf] = (rb >> 3) & 0x70;
        }
        int nr = wn * 64 + (lane >> 4) * 8 + (lane & 7);
#pragma unroll
        for (int fp = 0; fp < 4; fp++) {
            unsigned rb = (unsigned)((nr + fp * 16) * 128);
            bbase[fp] = rb;
            bmask[fp] = (rb >> 3) & 0x70;
        }
    }

    auto compute_chunk = [&](int stage) {
        unsigned sA = sbase + stage * STAGE_BYTES;
        unsigned sB = sA + A_STAGE_BYTES;
#pragma unroll
        for (int ks = 0; ks < 4; ks++) {
            unsigned a[2][4];
#pragma unroll
            for (int mf = 0; mf < 2; mf++) {
                unsigned addr = sA + abase[mf] + (((unsigned)(ks * 32) + aK) ^ amask[mf]);
                ldsm4(addr, a[mf][0], a[mf][1], a[mf][2], a[mf][3]);
            }
            unsigned b[8][2];
#pragma unroll
            for (int fp = 0; fp < 4; fp++) {
                unsigned addr = sB + bbase[fp] + (((unsigned)(ks * 32) + bK) ^ bmask[fp]);
                ldsm4(addr, b[2*fp][0], b[2*fp][1], b[2*fp+1][0], b[2*fp+1][1]);
            }
#pragma unroll
            for (int nf = 0; nf < 8; nf++)
#pragma unroll
                for (int mf = 0; mf < 2; mf++)
                    mma16816(c[nf][mf], a[mf], b[nf]);
        }
    };

    load_chunk(0, 0);
#pragma unroll 1
    for (int ck = 0; ck < NCH; ck++) {
        if (ck + 1 < NCH) { load_chunk(ck + 1, (ck + 1) & 1); cp_wait<1>(); }
        else              { cp_wait<0>(); }
        __syncthreads();
        compute_chunk(ck & 1);
        __syncthreads();
    }

    // ---- write accumulators to smem P tile (aliases stage buffers) ----
    float* P = (float*)smem;
    {
        int rbase = wm * 32 + (lane >> 2);
        int cbase = wn * 64 + (lane & 3) * 2;
#pragma unroll
        for (int nf = 0; nf < 8; nf++) {
#pragma unroll
            for (int mf = 0; mf < 2; mf++) {
                int col = cbase + nf * 8;
                int rr = rbase + mf * 16;
                *(float2*)&P[rr * PSTRIDE + col]       = make_float2(c[nf][mf][0], c[nf][mf][1]);
                *(float2*)&P[(rr + 8) * PSTRIDE + col] = make_float2(c[nf][mf][2], c[nf][mf][3]);
            }
        }
    }
    __syncthreads();

    if (mode == 0) {
        for (int idx = tid; idx < MV * HD; idx += 512) {
            int r = idx / HD + 1;
            int ch = idx % HD;
            int node = row0 + r - 1;
            if (node >= NN) continue;
            float h = P[r * PSTRIDE + ch] + bias1[ch];
            bf16 hi = __float2bfloat16(h);
            float lo = h - __bfloat162float(hi);
            size_t o = (size_t)t * RPAD * HD + (size_t)(node + 1) * HD + ch;
            Oh[o] = hi;
            Ol[o] = __float2bfloat16(lo);
        }
    } else {
        const float w0 = g_tw[layer*5+0], w1 = g_tw[layer*5+1], w2 = g_tw[layer*5+2],
                    w3 = g_tw[layer*5+3], w4 = g_tw[layer*5+4];
        const float* bc = g_bcat + (layer*4 + t) * 2048 + tn * BN;
        for (int idx = tid; idx < MV * 32; idx += 512) {
            int r = idx / 32 + 1;
            int jc = idx % 32;
            int node = row0 + r - 1;
            if (node >= NN) continue;
            int col = jc * 8;
            const float* Pr = P + r * PSTRIDE;
            float plin = Pr[col + 0];
            float prl  = Pr[col + 1];
            float pc   = Pr[col + 2 - PSTRIDE] + Pr[col + 3] + Pr[col + 4 + PSTRIDE];
            float prc  = Pr[col + 5 - PSTRIDE] + Pr[col + 6] + Pr[col + 7 + PSTRIDE];
            int jg = tn * 32 + jc;
            size_t ia = (size_t)(row0 + r) * HD + jg;  // plane-relative
            float hold = __bfloat162float(Ah[ia]) + __bfloat162float(Al[ia]);
            float h = w0 * fmaxf(plin + bc[col + 0], 0.f)
                    + w1 * fmaxf(prl  + bc[col + 1], 0.f)
                    + w2 * fmaxf(pc   + bc[col + 3], 0.f)
                    + w3 * fmaxf(prc  + bc[col + 6], 0.f)
                    + w4 * hold;
            bf16 hi = __float2bfloat16(h);
            float lo = h - __bfloat162float(hi);
            size_t o = (size_t)t * RPAD * HD + (size_t)(node + 1) * HD + jg;
            Oh[o] = hi;
            Ol[o] = __float2bfloat16(lo);
        }
    }
}

// ------------------- aggregation -------------------------------------------
__global__ void k_agg1() {
    int t = blockIdx.x >> 4;
    int chunk = blockIdx.x & 15;
    int ch = threadIdx.x;
    const bf16* Hh = g_Ahi + (size_t)t * RPAD * HD;
    const bf16* Hl = g_Alo + (size_t)t * RPAD * HD;
    float s = 0.f, mx = -3.4e38f;
    int n0 = chunk * 512;
    for (int n = n0; n < n0 + 512; n++) {
        size_t i = (size_t)(n + 1) * HD + ch;
        float v = __bfloat162float(Hh[i]) + __bfloat162float(Hl[i]);
        s += v;
        mx = fmaxf(mx, v);
    }
    g_psum[blockIdx.x * HD + ch] = s;
    g_pmax[blockIdx.x * HD + ch] = mx;
}

__global__ void k_agg2(const float* __restrict__ ow, const float* __restrict__ ob,
                       float* __restrict__ out) {
    __shared__ float agg[HD];
    int j = threadIdx.x;
    float s = 0.f, mx = -3.4e38f;
    for (int b = 0; b < 64; b++) {
        s += g_psum[b * HD + j];
        mx = fmaxf(mx, g_pmax[b * HD + j]);
    }
    agg[j] = g_aw[0] * s + g_aw[1] * (s / 32768.f) + g_aw[2] * mx;
    __syncthreads();
    if (j < 64) {
        float acc = ob[j];
        for (int k = 0; k < HD; k++) acc += agg[k] * ow[k * 64 + j];
        out[j] = acc;
    }
}

// ------------------- launcher ----------------------------------------------
extern "C" void kernel_launch(void* const* d_in, const int* in_sizes, int n_in,
                              void* d_out, int out_size) {
    (void)in_sizes; (void)n_in; (void)out_size;
    const float* x          = (const float*)d_in[0];
    const float* lin1_w     = (const float*)d_in[1];
    const float* lin1_b     = (const float*)d_in[2];
    const float* lin_w      = (const float*)d_in[3];
    const float* lin_b      = (const float*)d_in[4];
    const float* rel_lin_w  = (const float*)d_in[5];
    const float* rel_lin_b  = (const float*)d_in[6];
    const float* conv_w     = (const float*)d_in[7];
    const float* conv_b     = (const float*)d_in[8];
    const float* rel_conv_w = (const float*)d_in[9];
    const float* rel_conv_b = (const float*)d_in[10];
    const float* out_w      = (const float*)d_in[11];
    const float* out_b      = (const float*)d_in[12];
    const float* trans_arch = (const float*)d_in[13];
    const float* agg_arch   = (const float*)d_in[14];
    float* out = (float*)d_out;

    cudaFuncSetAttribute(k_gemm, cudaFuncAttributeMaxDynamicSharedMemorySize, SMEM_BYTES);

    k_prep<<<1, 32>>>(trans_arch, agg_arch);
    k_packx<<<4096, 256>>>(x);
    k_packw1<<<256, 256>>>(lin1_w);
    k_packwl<<<(8 * 2048 * 256 + 255) / 256, 256>>>(lin_w, lin_b, rel_lin_w, rel_lin_b,
                                                    conv_w, conv_b, rel_conv_w, rel_conv_b);

    dim3 g1(1, MT, TT), gl(8, MT, TT);
    // lin1: X -> A
    k_gemm<<<g1, 512, SMEM_BYTES>>>(0, 1, lin1_b, 0, 0);
    // layer 0: A -> B
    k_gemm<<<gl, 512, SMEM_BYTES>>>(1, 2, nullptr, 1, 0);
    // layer 1: B -> A
    k_gemm<<<gl, 512, SMEM_BYTES>>>(2, 1, nullptr, 1, 1);

    k_agg1<<<64, 256>>>();
    k_agg2<<<1, 256>>>(out_w, out_b, out);
}